// round 6
// baseline (speedup 1.0000x reference)
#include <cuda_runtime.h>
#include <cuda_bf16.h>
#include <cstdint>

// ---------------------------------------------------------------------------
// GCN graph conv:
//   out_deg = clip(segsum(1, src), 1);  in_deg = clip(segsum(1, dst), 1)
//   h   = tanh( (feat * out_deg^-0.5) @ W )            [N, 128]
//   out = segsum( h[src] * ew , dst ) * in_deg^-0.5    [N, 128]
//
// NOTE: src/dst buffers are INT32 (jax default x64-disabled randint), despite
// the reference's jnp.int64 annotation. Reading them as int64 produces wild
// addresses -> error 717. Cast to const int*.
// ---------------------------------------------------------------------------

#define IN_FEATS  256
#define OUT_FEATS 128
#define MAX_N     100000

__device__ int   g_outdeg[MAX_N];
__device__ int   g_indeg [MAX_N];
__device__ __align__(16) float g_h[(size_t)MAX_N * OUT_FEATS];

// ---------------------------------------------------------------------------
__global__ void zero_deg_kernel(int n) {
    int i = blockIdx.x * blockDim.x + threadIdx.x;
    if (i < n) { g_outdeg[i] = 0; g_indeg[i] = 0; }
}

__global__ void degree_kernel(const int* __restrict__ src,
                              const int* __restrict__ dst, int E) {
    int e = blockIdx.x * blockDim.x + threadIdx.x;
    if (e < E) {
        atomicAdd(&g_outdeg[src[e]], 1);
        atomicAdd(&g_indeg [dst[e]], 1);
    }
}

// ---------------------------------------------------------------------------
// SGEMM with fused out-degree pre-scale on A and tanh epilogue.
// Tile: 128x128, BK=8, 256 threads, 8x8 per thread.
#define BM 128
#define BN 128
#define BK 8
#define TM 8
#define TN 8

__global__ __launch_bounds__(256)
void gemm_tanh_kernel(const float* __restrict__ feat,
                      const float* __restrict__ W, int M) {
    __shared__ __align__(16) float As[BK][BM];
    __shared__ __align__(16) float Bs[BK][BN];

    const int t    = threadIdx.x;
    const int row0 = blockIdx.x * BM;
    const int tx   = t & 15;      // 0..15 -> 8 cols each
    const int ty   = t >> 4;      // 0..15 -> 8 rows each

    // A-loader: thread t loads feat[row0 + t/2][k0 + (t&1)*4 .. +3]
    const int arow = t >> 1;
    const int acol = (t & 1) * 4;
    float ascale = 0.0f;
    const bool arow_ok = (row0 + arow) < M;
    if (arow_ok) {
        int dg = g_outdeg[row0 + arow];
        ascale = rsqrtf((float)(dg > 0 ? dg : 1));
    }
    // B-loader: thread t loads W[k0 + t/32][(t&31)*4 .. +3]
    const int bk = t >> 5;
    const int bn = (t & 31) * 4;

    float acc[TM][TN];
#pragma unroll
    for (int i = 0; i < TM; ++i)
#pragma unroll
        for (int j = 0; j < TN; ++j) acc[i][j] = 0.0f;

    for (int k0 = 0; k0 < IN_FEATS; k0 += BK) {
        float4 av = make_float4(0.f, 0.f, 0.f, 0.f);
        if (arow_ok)
            av = *(const float4*)(feat + (size_t)(row0 + arow) * IN_FEATS + k0 + acol);
        As[acol + 0][arow] = av.x * ascale;
        As[acol + 1][arow] = av.y * ascale;
        As[acol + 2][arow] = av.z * ascale;
        As[acol + 3][arow] = av.w * ascale;

        float4 bv = *(const float4*)(W + (size_t)(k0 + bk) * OUT_FEATS + bn);
        *(float4*)&Bs[bk][bn] = bv;

        __syncthreads();

#pragma unroll
        for (int k = 0; k < BK; ++k) {
            float ra[TM], rb[TN];
#pragma unroll
            for (int i = 0; i < TM; ++i) ra[i] = As[k][ty * TM + i];
#pragma unroll
            for (int j = 0; j < TN; ++j) rb[j] = Bs[k][tx * TN + j];
#pragma unroll
            for (int i = 0; i < TM; ++i)
#pragma unroll
                for (int j = 0; j < TN; ++j) acc[i][j] += ra[i] * rb[j];
        }
        __syncthreads();
    }

    // tanh epilogue + store to g_h
#pragma unroll
    for (int i = 0; i < TM; ++i) {
        int r = row0 + ty * TM + i;
        if (r < M) {
            float* dstp = g_h + (size_t)r * OUT_FEATS + tx * TN;
            float4 o0, o1;
            o0.x = tanhf(acc[i][0]); o0.y = tanhf(acc[i][1]);
            o0.z = tanhf(acc[i][2]); o0.w = tanhf(acc[i][3]);
            o1.x = tanhf(acc[i][4]); o1.y = tanhf(acc[i][5]);
            o1.z = tanhf(acc[i][6]); o1.w = tanhf(acc[i][7]);
            *(float4*)(dstp)     = o0;
            *(float4*)(dstp + 4) = o1;
        }
    }
}

// ---------------------------------------------------------------------------
// One warp per edge. lane -> one float4 (4 of 128 feats): vector gather,
// scale, vector 128-bit atomicAdd into out (sm_90+ intrinsic).
// Folds in_deg^-0.5 of the destination into the edge weight so no post-pass.
__global__ __launch_bounds__(256)
void scatter_kernel(const int* __restrict__ src,
                    const int* __restrict__ dst,
                    const float* __restrict__ ew,
                    float* __restrict__ out, int E) {
    const int lane = threadIdx.x & 31;
    const int e = blockIdx.x * (blockDim.x >> 5) + (threadIdx.x >> 5);
    if (e >= E) return;

    const int s = __ldg(src + e);
    const int d = __ldg(dst + e);
    const int dg = __ldg(&g_indeg[d]);
    const float w = __ldg(ew + e) * rsqrtf((float)(dg > 0 ? dg : 1));

    float4 v = __ldg((const float4*)g_h + (size_t)s * (OUT_FEATS / 4) + lane);
    v.x *= w; v.y *= w; v.z *= w; v.w *= w;

    float4* p = (float4*)(out + (size_t)d * OUT_FEATS) + lane;
#if __CUDA_ARCH__ >= 900
    atomicAdd(p, v);
#else
    float* ps = (float*)p;
    atomicAdd(ps + 0, v.x);
    atomicAdd(ps + 1, v.y);
    atomicAdd(ps + 2, v.z);
    atomicAdd(ps + 3, v.w);
#endif
}

// ---------------------------------------------------------------------------
__global__ void zero_out_kernel(float* __restrict__ out, int n) {
    int i = blockIdx.x * blockDim.x + threadIdx.x;
    if (i < n) out[i] = 0.0f;
}

// ---------------------------------------------------------------------------
extern "C" void kernel_launch(void* const* d_in, const int* in_sizes, int n_in,
                              void* d_out, int out_size) {
    const float* feat = (const float*)d_in[0];
    const float* W    = (const float*)d_in[1];
    const float* ew   = (const float*)d_in[2];
    const int*   src  = (const int*)d_in[3];   // int32 on device (jax x64 off)
    const int*   dst  = (const int*)d_in[4];
    float*       out  = (float*)d_out;

    const int M = in_sizes[0] / IN_FEATS;   // 100000
    const int E = in_sizes[2];              // 1600000

    zero_deg_kernel<<<(M + 255) / 256, 256>>>(M);
    degree_kernel<<<(E + 255) / 256, 256>>>(src, dst, E);
    gemm_tanh_kernel<<<(M + BM - 1) / BM, 256>>>(feat, W, M);
    zero_out_kernel<<<(out_size + 255) / 256, 256>>>(out, out_size);
    {
        const int warps_per_block = 256 / 32;
        const int blocks = (E + warps_per_block - 1) / warps_per_block;
        scatter_kernel<<<blocks, 256>>>(src, dst, ew, out, E);
    }
}